// round 4
// baseline (speedup 1.0000x reference)
#include <cuda_runtime.h>
#include <cstdint>
#include <cstddef>

#define NB     32
#define NLAT   721
#define NLON   1440
#define NVEC   360          // NLON / 4
#define NWORDS 45           // NLON / 32
#define NTH    128
#define NROWS  (NB * NLAT)  // 23072
#define GRID   1480         // 148 SMs * 10 resident CTAs -> single wave

// Cross-kernel scratch (no allocations allowed).
__device__ int g_row_valid[NROWS];

__device__ __forceinline__ bool nan_f(float x) {
    return (__float_as_uint(x) & 0x7FFFFFFFu) > 0x7F800000u;
}

// Butterfly-combine 4-bit validity nibbles across groups of 8 lanes into a
// 32-bit mask word (bit 4k+j = validity of element 4*(group_base+k)+j).
__device__ __forceinline__ unsigned combine8(unsigned v, int lane) {
    unsigned o = __shfl_xor_sync(0xFFFFFFFFu, v, 1);
    v = (lane & 1) ? ((v << 4) | o) : ((o << 4) | v);
    o = __shfl_xor_sync(0xFFFFFFFFu, v, 2);
    v = (lane & 2) ? ((v << 8) | o) : ((o << 8) | v);
    o = __shfl_xor_sync(0xFFFFFFFFu, v, 4);
    v = (lane & 4) ? ((v << 16) | o) : ((o << 16) | v);
    return v;
}

__device__ __forceinline__ unsigned nib_of(float4 r) {
    return (unsigned)(!nan_f(r.x))        | ((unsigned)(!nan_f(r.y)) << 1)
         | ((unsigned)(!nan_f(r.z)) << 2) | ((unsigned)(!nan_f(r.w)) << 3);
}

// Interp one NaN element i given 64-bit low/high windows around its word.
// lo64 = (mask[w]<<32)|mask[w-1], hi64 = (mask[w+1]<<32)|mask[w].
__device__ __forceinline__ float interp_elem(
    int i, int w, unsigned long long lo64, unsigned long long hi64,
    const unsigned* __restrict__ mask, const float* __restrict__ s,
    int firstv, int lastv)
{
    const int bpos = i & 31;

    unsigned long long lm = lo64 & (0xFFFFFFFFFFFFFFFFull >> (31 - bpos));
    int prev;
    if (lm) {
        prev = ((w - 1) << 5) + 63 - __clzll(lm);
    } else {
        prev = lastv - NLON;                        // circular wrap
        #pragma unroll 1
        for (int ww = w - 2; ww >= 0; ww--) {
            unsigned mw = mask[ww];
            if (mw) { prev = (ww << 5) + 31 - __clz(mw); break; }
        }
    }

    unsigned long long hm = hi64 & (0xFFFFFFFFFFFFFFFFull << bpos);
    int nxt;
    if (hm) {
        nxt = (w << 5) + __ffsll(hm) - 1;
    } else {
        nxt = firstv + NLON;                        // circular wrap
        #pragma unroll 1
        for (int ww = w + 2; ww < NWORDS; ww++) {
            unsigned mw = mask[ww];
            if (mw) { nxt = (ww << 5) + __ffs(mw) - 1; break; }
        }
    }

    const int dtot = nxt - prev;                    // > 0 when row valid
    const float t  = __fdividef((float)(i - prev), (float)dtot);
    const int pm = (prev < 0)     ? prev + NLON : prev;
    const int nm = (nxt >= NLON)  ? nxt  - NLON : nxt;
    const float sp = s[pm];
    const float sn = s[nm];
    return fmaf(t, sn - sp, sp);
}

// ---------------------------------------------------------------------------
// Kernel A: persistent CTAs, grid-stride over rows, prefetch next row's
// loads during current row's interp. Single wave -> no wave transitions.
// ---------------------------------------------------------------------------
__global__ void __launch_bounds__(NTH, 10)
fill_rows_kernel(const float4* __restrict__ sst4, float* __restrict__ out)
{
    __shared__ float    s[NLON];
    __shared__ unsigned mask[NWORDS];

    const int t    = threadIdx.x;
    const int lane = t & 31;
    const bool has2 = (t < NVEC - 256);             // t < 104

    int row = blockIdx.x;

    // Prologue: load first row into registers.
    float4 r0 = make_float4(0,0,0,0), r1 = r0, r2 = r0;
    if (row < NROWS) {
        const float4* __restrict__ src = sst4 + (size_t)row * NVEC;
        r0 = src[t];
        r1 = src[t + 128];
        if (has2) r2 = src[t + 256];
    }

    for (; row < NROWS; row += GRID) {
        __syncthreads();                            // smem free from prev iter

        ((float4*)s)[t]       = r0;
        ((float4*)s)[t + 128] = r1;
        if (has2) ((float4*)s)[t + 256] = r2;

        // Validity mask from registers (no LDS, no ballots).
        unsigned w0 = combine8(nib_of(r0), lane);
        unsigned w1 = combine8(nib_of(r1), lane);
        unsigned w2 = combine8(has2 ? nib_of(r2) : 0u, lane);
        if ((lane & 7) == 0) {
            const int widx = t >> 3;                // 0..15
            mask[widx]      = w0;
            mask[widx + 16] = w1;
            if (widx + 32 < NWORDS) mask[widx + 32] = w2;
        }
        __syncthreads();

        // first/last valid index: redundant per warp (2 ballots + shfl).
        const unsigned mwa = (lane < NWORDS)      ? mask[lane]      : 0u;
        const unsigned mwb = (lane + 32 < NWORDS) ? mask[lane + 32] : 0u;
        const unsigned b1 = __ballot_sync(0xFFFFFFFFu, mwa != 0u);
        const unsigned b2 = __ballot_sync(0xFFFFFFFFu, mwb != 0u);
        const bool rv = (b1 | b2) != 0u;

        int firstv = 0, lastv = 0;
        if (rv) {
            const int fw = b1 ? (__ffs(b1) - 1) : (31 + __ffs(b2));
            const unsigned fm = __shfl_sync(0xFFFFFFFFu, (fw < 32) ? mwa : mwb, fw & 31);
            firstv = (fw << 5) + __ffs(fm) - 1;
            const int lw = b2 ? (63 - __clz(b2)) : (31 - __clz(b1));
            const unsigned lm = __shfl_sync(0xFFFFFFFFu, (lw < 32) ? mwa : mwb, lw & 31);
            lastv = (lw << 5) + 31 - __clz(lm);
        }
        if (t == 0) g_row_valid[row] = rv ? 1 : 0;

        // Prefetch next row (independent; overlaps interp below).
        const int nrow = row + GRID;
        float4 p0 = make_float4(0,0,0,0), p1 = p0, p2 = p0;
        if (nrow < NROWS) {
            const float4* __restrict__ nsrc = sst4 + (size_t)nrow * NVEC;
            p0 = nsrc[t];
            p1 = nsrc[t + 128];
            if (has2) p2 = nsrc[t + 256];
        }

        // Interpolate current row from registers + smem gathers, STG.128 out.
        float4* __restrict__ dst = (float4*)(out + (size_t)row * NLON);
        #pragma unroll
        for (int k = 0; k < 3; k++) {
            if (k == 2 && !has2) break;
            const int vec  = t + k * NTH;
            const int base = vec << 2;
            const int w    = base >> 5;
            float4 r = (k == 0) ? r0 : (k == 1) ? r1 : r2;

            if (rv) {
                const unsigned cur = mask[w];
                const unsigned lo  = (w > 0)          ? mask[w - 1] : 0u;
                const unsigned hi  = (w < NWORDS - 1) ? mask[w + 1] : 0u;
                const unsigned long long lo64 = ((unsigned long long)cur << 32) | lo;
                const unsigned long long hi64 = ((unsigned long long)hi  << 32) | cur;

                if (nan_f(r.x)) r.x = interp_elem(base + 0, w, lo64, hi64, mask, s, firstv, lastv);
                if (nan_f(r.y)) r.y = interp_elem(base + 1, w, lo64, hi64, mask, s, firstv, lastv);
                if (nan_f(r.z)) r.z = interp_elem(base + 2, w, lo64, hi64, mask, s, firstv, lastv);
                if (nan_f(r.w)) r.w = interp_elem(base + 3, w, lo64, hi64, mask, s, firstv, lastv);
            }
            dst[vec] = r;
        }

        r0 = p0; r1 = p1; r2 = p2;
    }
}

// ---------------------------------------------------------------------------
// Kernel B: polar fill. Common case: lastrow == NLAT-1 -> immediate exit.
// ---------------------------------------------------------------------------
__global__ void __launch_bounds__(256)
fill_polar_kernel(const float* __restrict__ sst, float* __restrict__ out)
{
    const int b = blockIdx.x;
    const int tid = threadIdx.x;

    __shared__ int s_lastrow;
    if (tid == 0) s_lastrow = -1;
    __syncthreads();

    int loc = -1;
    for (int h = tid; h < NLAT; h += 256)
        if (g_row_valid[b * NLAT + h]) loc = (h > loc) ? h : loc;
    if (loc >= 0) atomicMax(&s_lastrow, loc);
    __syncthreads();

    const int lastrow = s_lastrow;
    if (lastrow < 0 || lastrow >= NLAT - 1) return;

    __shared__ float    s[NLON];
    __shared__ float    f[NLON];
    __shared__ unsigned mask[NWORDS];
    __shared__ int      s_first, s_last;

    const float* __restrict__ srow = sst + ((size_t)b * NLAT + lastrow) * NLON;

    for (int i = tid; i < NLON; i += 256) s[i] = srow[i];
    __syncthreads();

    #pragma unroll
    for (int k = 0; k < 6; k++) {
        const int i = k * 256 + tid;
        const bool inb = (i < NLON);
        const bool valid = inb && !nan_f(inb ? s[i] : 0.0f);
        const unsigned bal = __ballot_sync(0xFFFFFFFFu, valid);
        if ((tid & 31) == 0) {
            const int w = i >> 5;
            if (w < NWORDS) mask[w] = bal;
        }
    }
    __syncthreads();

    if (tid == 0) {
        int ff = -1, la = -1;
        #pragma unroll 1
        for (int w = 0; w < NWORDS; w++) {
            unsigned mw = mask[w];
            if (mw) { ff = (w << 5) + __ffs(mw) - 1; break; }
        }
        #pragma unroll 1
        for (int w = NWORDS - 1; w >= 0; w--) {
            unsigned mw = mask[w];
            if (mw) { la = (w << 5) + 31 - __clz(mw); break; }
        }
        s_first = ff; s_last = la;
    }
    __syncthreads();

    for (int i = tid; i < NLON; i += 256) {
        const int w = i >> 5;
        const unsigned cur = mask[w];
        const unsigned lo  = (w > 0)          ? mask[w - 1] : 0u;
        const unsigned hi  = (w < NWORDS - 1) ? mask[w + 1] : 0u;
        const unsigned long long lo64 = ((unsigned long long)cur << 32) | lo;
        const unsigned long long hi64 = ((unsigned long long)hi  << 32) | cur;
        f[i] = interp_elem(i, w, lo64, hi64, mask, s, s_first, s_last);
    }
    __syncthreads();

    for (int h = lastrow + 1; h < NLAT; h++) {
        const float* __restrict__ sr   = sst + ((size_t)b * NLAT + h) * NLON;
        float*       __restrict__ orow = out + ((size_t)b * NLAT + h) * NLON;
        for (int i = tid; i < NLON; i += 256) {
            if (nan_f(sr[i])) orow[i] = f[i];
        }
    }
}

// ---------------------------------------------------------------------------
extern "C" void kernel_launch(void* const* d_in, const int* in_sizes, int n_in,
                              void* d_out, int out_size)
{
    const float* sst = (const float*)d_in[0];
    float*       out = (float*)d_out;

    fill_rows_kernel<<<GRID, NTH>>>((const float4*)sst, out);
    fill_polar_kernel<<<NB, 256>>>(sst, out);
}

// round 5
// speedup vs baseline: 1.7136x; 1.7136x over previous
#include <cuda_runtime.h>
#include <cstdint>
#include <cstddef>

#define NB     32
#define NLAT   721
#define NLON   1440
#define NVEC   360          // NLON / 4
#define NWORDS 45           // NLON / 32
#define NTH    128
#define NROWS  (NB * NLAT)  // 23072

// Cross-CTA scratch (no allocations allowed).
__device__ int g_row_valid[NROWS];
__device__ int g_ticket = 0;

__device__ __forceinline__ bool nan_f(float x) {
    return (__float_as_uint(x) & 0x7FFFFFFFu) > 0x7F800000u;
}

// Butterfly-combine 4-bit validity nibbles across groups of 8 lanes into a
// 32-bit mask word (bit 4k+j = validity of element 4*(group_base+k)+j).
__device__ __forceinline__ unsigned combine8(unsigned v, int lane) {
    unsigned o = __shfl_xor_sync(0xFFFFFFFFu, v, 1);
    v = (lane & 1) ? ((v << 4) | o) : ((o << 4) | v);
    o = __shfl_xor_sync(0xFFFFFFFFu, v, 2);
    v = (lane & 2) ? ((v << 8) | o) : ((o << 8) | v);
    o = __shfl_xor_sync(0xFFFFFFFFu, v, 4);
    v = (lane & 4) ? ((v << 16) | o) : ((o << 16) | v);
    return v;
}

__device__ __forceinline__ unsigned nib_of(float4 r) {
    return (unsigned)(!nan_f(r.x))        | ((unsigned)(!nan_f(r.y)) << 1)
         | ((unsigned)(!nan_f(r.z)) << 2) | ((unsigned)(!nan_f(r.w)) << 3);
}

// ---------------------------------------------------------------------------
// Single fused kernel: one CTA per (b,lat) row; last CTA does the polar fill.
// Interp is computed branch-free for EVERY element:
//   valid element  -> prev==next==i -> t==0 -> result == s[i] (exact)
//   NaN element    -> linear interp between prev/next valid (circular)
// ---------------------------------------------------------------------------
__global__ void __launch_bounds__(NTH)
fill_kernel(const float4* __restrict__ sst4, const float* __restrict__ sst,
            float* __restrict__ out)
{
    __shared__ float    s[NLON];
    __shared__ unsigned mask[NWORDS];
    __shared__ int      Ptab[NWORDS];   // prev valid idx strictly before word w (wrap-adj)
    __shared__ int      Ntab[NWORDS];   // next valid idx strictly after  word w (wrap-adj)
    __shared__ int      s_is_last;

    const int row  = blockIdx.x;        // b * NLAT + h
    const int t    = threadIdx.x;
    const int lane = t & 31;
    const bool has2 = (t < NVEC - 256); // t < 104

    const float4* __restrict__ src = sst4 + (size_t)row * NVEC;
    float4*       __restrict__ dst = (float4*)(out + (size_t)row * NLON);

    // ---- Front-batched loads (3 independent LDG.128) ----
    float4 r0 = src[t];
    float4 r1 = src[t + 128];
    float4 r2 = make_float4(0.f, 0.f, 0.f, 0.f);
    if (has2) r2 = src[t + 256];

    ((float4*)s)[t]       = r0;
    ((float4*)s)[t + 128] = r1;
    if (has2) ((float4*)s)[t + 256] = r2;

    // ---- Validity mask words from registers ----
    unsigned w0 = combine8(nib_of(r0), lane);
    unsigned w1 = combine8(nib_of(r1), lane);
    unsigned w2 = combine8(has2 ? nib_of(r2) : 0u, lane);
    if ((lane & 7) == 0) {
        const int widx = t >> 3;        // 0..15
        mask[widx]      = w0;
        mask[widx + 16] = w1;
        if (widx + 32 < NWORDS) mask[widx + 32] = w2;
    }
    __syncthreads();

    // ---- Word-validity bitmap B (redundant per warp: 2 ballots) ----
    const unsigned mwa = (lane < NWORDS)      ? mask[lane]      : 0u;
    const unsigned mwb = (lane + 32 < NWORDS) ? mask[lane + 32] : 0u;
    const unsigned b1 = __ballot_sync(0xFFFFFFFFu, mwa != 0u);
    const unsigned b2 = __ballot_sync(0xFFFFFFFFu, mwb != 0u);
    const unsigned long long B = ((unsigned long long)b2 << 32) | b1;
    const bool rv = (B != 0ull);

    if (t == 0) g_row_valid[row] = rv ? 1 : 0;

    // ---- Per-word prev/next tables (threads 0..44, ~10 ops each) ----
    if (rv && t < NWORDS) {
        const int fw = __ffsll((long long)B) - 1;
        const int firstv = (fw << 5) + __ffs(mask[fw]) - 1;
        const int lw = 63 - __clzll((long long)B);
        const int lastv  = (lw << 5) + 31 - __clz(mask[lw]);

        const unsigned long long lowB  = B & ((1ull << t) - 1ull);
        int pv = lastv - NLON;                         // circular wrap
        if (lowB) {
            const int pw = 63 - __clzll((long long)lowB);
            pv = (pw << 5) + 31 - __clz(mask[pw]);
        }
        Ptab[t] = pv;

        const unsigned long long highB = B >> (t + 1);
        int nv = firstv + NLON;                        // circular wrap
        if (highB) {
            const int nw = (t + 1) + __ffsll((long long)highB) - 1;
            nv = (nw << 5) + __ffs(mask[nw]) - 1;
        }
        Ntab[t] = nv;
    }
    __syncthreads();

    // ---- Branch-free interpolation for all elements ----
    if (rv) {
        const int bpos0 = (t & 7) << 2;                // element bit offset in word
        #pragma unroll
        for (int k = 0; k < 3; k++) {
            if (k == 2 && !has2) break;
            const int vec   = t + k * NTH;
            const int w     = vec >> 3;
            const int wbase = w << 5;
            const unsigned cur = mask[w];              // LDS (8-lane broadcast)
            const int Pw = Ptab[w];
            const int Nw = Ntab[w];

            float res[4];
            #pragma unroll
            for (int c = 0; c < 4; c++) {
                const int bpos = bpos0 + c;
                const int i    = wbase + bpos;

                const unsigned lm = cur & (0xFFFFFFFFu >> (31 - bpos));
                const int prev = lm ? (wbase + 31 - __clz(lm)) : Pw;
                const unsigned hm = cur & (0xFFFFFFFFu << bpos);
                const int nxt  = hm ? (wbase + __ffs(hm) - 1) : Nw;

                const int dtot = nxt - prev;           // 0 iff element valid
                const float tt = (dtot > 0)
                               ? __fdividef((float)(i - prev), (float)dtot) : 0.0f;
                const int pm = (prev < 0)    ? prev + NLON : prev;
                const int nm = (nxt >= NLON) ? nxt  - NLON : nxt;
                const float sp = s[pm];
                const float sn = s[nm];
                res[c] = fmaf(tt, sn - sp, sp);        // == sp == s[i] when valid
            }
            dst[vec] = make_float4(res[0], res[1], res[2], res[3]);
        }
    } else {
        // Row has no valid sample: output stays NaN-pattern = input row.
        dst[t]       = r0;
        dst[t + 128] = r1;
        if (has2) dst[t + 256] = r2;
    }

    // ---- Last-CTA polar fill (ticket pattern; graph-capturable) ----
    __threadfence();
    __syncthreads();
    if (t == 0) {
        const int ticket = atomicAdd(&g_ticket, 1);
        s_is_last = (ticket == (int)gridDim.x - 1) ? 1 : 0;
    }
    __syncthreads();
    if (!s_is_last) return;

    // We are the last CTA: all rows written & visible.
    for (int b = 0; b < NB; b++) {
        int lr = NLAT - 1;
        while (lr >= 0 && !g_row_valid[b * NLAT + lr]) lr--;
        if (lr < 0 || lr == NLAT - 1) continue;        // common case: continue

        // Fill value row: out[b, lr, :] equals the reference's interpolated v.
        const float* __restrict__ fill = out + ((size_t)b * NLAT + lr) * NLON;
        for (int h = lr + 1; h < NLAT; h++) {
            const float* __restrict__ sr   = sst + ((size_t)b * NLAT + h) * NLON;
            float*       __restrict__ orow = out + ((size_t)b * NLAT + h) * NLON;
            for (int i = t; i < NLON; i += NTH) {
                if (nan_f(sr[i])) orow[i] = fill[i];
            }
        }
    }
    if (t == 0) g_ticket = 0;                          // reset for next replay
}

// ---------------------------------------------------------------------------
extern "C" void kernel_launch(void* const* d_in, const int* in_sizes, int n_in,
                              void* d_out, int out_size)
{
    const float* sst = (const float*)d_in[0];
    float*       out = (float*)d_out;

    fill_kernel<<<NROWS, NTH>>>((const float4*)sst, sst, out);
}